// round 6
// baseline (speedup 1.0000x reference)
#include <cuda_runtime.h>
#include <cuda_bf16.h>
#include <cstdint>

#define NB 200000
#define NC 20000
#define NT 2000
#define DD 128
#define EADJ_MAX 1600000

// ---------------- scratch (device globals; no allocation allowed) ------------
__device__ float g_hs1[(size_t)NB * DD];
__device__ float g_xwg[(size_t)NB * DD];
__device__ float g_hd1[(size_t)NC * DD];
__device__ float g_hs2[(size_t)NC * DD];
__device__ float g_num1[(size_t)NC * DD];
__device__ float g_hd2[(size_t)NT * DD];
__device__ float g_num2[(size_t)NT * DD];
__device__ float g_es1[NB * 4];
__device__ float g_ed1[NC * 4];
__device__ float g_es2[NC * 4];
__device__ float g_ed2[NT * 4];
__device__ float g_m1[NC * 4];
__device__ float g_s1[NC * 4];
__device__ float g_m2[NT * 4];
__device__ float g_s2[NT * 4];
__device__ float g_e1[200000 * 4];
__device__ float g_e2[20000 * 4];
__device__ float g_dinv[NB];
__device__ int   g_degi[NB];
__device__ int   g_off[NB + 1];
__device__ int   g_cursor[NB];
__device__ int   g_csrc[EADJ_MAX];
__device__ int   g_bsum[512];

// ---------------- helpers ----------------------------------------------------
__device__ __forceinline__ void redAddV4(float* p, float a, float b, float c, float d) {
    asm volatile("red.global.add.v4.f32 [%0], {%1,%2,%3,%4};"
                 :: "l"(p), "f"(a), "f"(b), "f"(c), "f"(d) : "memory");
}
__device__ __forceinline__ void atomicMaxFloat(float* addr, float v) {
    if (v >= 0.0f) atomicMax((int*)addr, __float_as_int(v));
    else atomicMin((unsigned int*)addr, (unsigned int)__float_as_int(v));
}
__device__ __forceinline__ uint32_t smem_u32(const void* p) {
    uint32_t a;
    asm("{ .reg .u64 t; cvta.to.shared.u64 t, %1; cvt.u32.u64 %0, t; }" : "=r"(a) : "l"(p));
    return a;
}
__device__ __forceinline__ void split2(float a, float b, uint32_t& hi, uint32_t& lo) {
    __nv_bfloat16 ah = __float2bfloat16(a), bh = __float2bfloat16(b);
    __nv_bfloat16 al = __float2bfloat16(a - __bfloat162float(ah));
    __nv_bfloat16 bl = __float2bfloat16(b - __bfloat162float(bh));
    __nv_bfloat162 H; H.x = ah; H.y = bh;
    __nv_bfloat162 L; L.x = al; L.y = bl;
    hi = *(uint32_t*)&H; lo = *(uint32_t*)&L;
}

#define LDSM4(r, addr) \
    asm volatile("ldmatrix.sync.aligned.m8n8.x4.shared.b16 {%0,%1,%2,%3}, [%4];" \
                 : "=r"((r)[0]), "=r"((r)[1]), "=r"((r)[2]), "=r"((r)[3]) : "r"(addr))
#define LDSM4T(r, addr) \
    asm volatile("ldmatrix.sync.aligned.m8n8.x4.trans.shared.b16 {%0,%1,%2,%3}, [%4];" \
                 : "=r"((r)[0]), "=r"((r)[1]), "=r"((r)[2]), "=r"((r)[3]) : "r"(addr))
#define MMA16816(c, a, b0, b1) \
    asm volatile("mma.sync.aligned.m16n8k16.row.col.f32.bf16.bf16.f32 " \
                 "{%0,%1,%2,%3}, {%4,%5,%6,%7}, {%8,%9}, {%0,%1,%2,%3};" \
                 : "+f"((c)[0]), "+f"((c)[1]), "+f"((c)[2]), "+f"((c)[3]) \
                 : "r"((a)[0]), "r"((a)[1]), "r"((a)[2]), "r"((a)[3]), "r"(b0), "r"(b1))

// ---------------- init --------------------------------------------------------
__global__ void init_kernel() {
    int idx = blockIdx.x * blockDim.x + threadIdx.x;
    int stride = gridDim.x * blockDim.x;
    float4 z = make_float4(0.f, 0.f, 0.f, 0.f);
    for (int i = idx; i < NC * DD / 4; i += stride) ((float4*)g_num1)[i] = z;
    for (int i = idx; i < NT * DD / 4; i += stride) ((float4*)g_num2)[i] = z;
    for (int i = idx; i < NB; i += stride) { g_degi[i] = 0; g_cursor[i] = 0; }
    for (int i = idx; i < NC * 4; i += stride) { g_s1[i] = 0.f; g_m1[i] = -1e30f; }
    for (int i = idx; i < NT * 4; i += stride) { g_s2[i] = 0.f; g_m2[i] = -1e30f; }
}

// ---------------- bf16-split tensor-core GEMM --------------------------------
// O[M,NCOLS] = X[M,128] @ [W0 | W1], fp32 via 3-term bf16 split mma.sync.
// Warps: 4 row-groups x (NCOLS/64) col-groups, warp tile 32x64.
// Fused alpha: aout[row*4+h] = dot(O0[row, h*32..], avec[h*32..]) for cols<128.
template <int NCOLS>
__global__ void __launch_bounds__((NCOLS == 256) ? 512 : 256, 1)
mma_gemm(const float* __restrict__ X, int M, int ntiles,
         const float* __restrict__ W0, const float* __restrict__ W1,
         float* __restrict__ O0, float* __restrict__ O1,
         const float* __restrict__ avec, float* __restrict__ aout) {
    constexpr int NTH = (NCOLS == 256) ? 512 : 256;
    constexpr int SA = 136;            // A row stride in halfs (128 + 8 pad)
    constexpr int SW = NCOLS + 8;      // W row stride in halfs
    constexpr int AHI = 0;
    constexpr int ALO = 128 * SA;
    constexpr int WHI = 2 * 128 * SA;
    constexpr int WLO = WHI + 128 * SW;
    constexpr int ABYTES = 2 * (WLO + 128 * SW);

    extern __shared__ __nv_bfloat16 sh[];
    float* aS = (float*)((char*)sh + ABYTES);
    const int tid = threadIdx.x;
    const int lane = tid & 31;
    const int w = tid >> 5;
    const int wr = (w & 3) * 32;
    const int wc = (w >> 2) * 64;
    const uint32_t sbase = smem_u32(sh);

    // load + split W into smem (once)
    for (int idx = tid; idx < 128 * (NCOLS / 4); idx += NTH) {
        int k = idx / (NCOLS / 4);
        int n4 = (idx % (NCOLS / 4)) * 4;
        const float* src = (NCOLS == 256 && n4 >= 128) ? &W1[k * 128 + n4 - 128]
                                                       : &W0[k * 128 + n4];
        float4 v = *(const float4*)src;
        uint2 hv, lv;
        split2(v.x, v.y, hv.x, lv.x);
        split2(v.z, v.w, hv.y, lv.y);
        *(uint2*)&sh[WHI + k * SW + n4] = hv;
        *(uint2*)&sh[WLO + k * SW + n4] = lv;
    }
    if (aout && tid < 128) aS[tid] = avec[tid];

    const int laneR = lane & 15;
    const int laneC = (lane >> 4) << 3;

    for (int tile = blockIdx.x; tile < ntiles; tile += gridDim.x) {
        const int row0 = tile * 128;
        __syncthreads();
        // load + split X tile
        for (int idx = tid; idx < 4096; idx += NTH) {
            int r = idx >> 5;
            int c4 = (idx & 31) * 4;
            uint2 hv = make_uint2(0, 0), lv = make_uint2(0, 0);
            if (row0 + r < M) {
                float4 v = *(const float4*)&X[(size_t)(row0 + r) * 128 + c4];
                split2(v.x, v.y, hv.x, lv.x);
                split2(v.z, v.w, hv.y, lv.y);
            }
            *(uint2*)&sh[AHI + r * SA + c4] = hv;
            *(uint2*)&sh[ALO + r * SA + c4] = lv;
        }
        __syncthreads();

        float acc[2][8][4];
        #pragma unroll
        for (int mi = 0; mi < 2; mi++)
            #pragma unroll
            for (int j = 0; j < 8; j++)
                #pragma unroll
                for (int t = 0; t < 4; t++) acc[mi][j][t] = 0.f;

        #pragma unroll
        for (int term = 0; term < 3; term++) {
            const int aoff = (term == 2) ? ALO : AHI;
            const int woff = (term == 1) ? WLO : WHI;
            const uint32_t aBase = sbase + 2u * (aoff + (wr + laneR) * SA + laneC);
            const uint32_t bBase = sbase + 2u * (woff + laneR * SW + wc + laneC);
            #pragma unroll
            for (int ks = 0; ks < 8; ks++) {
                uint32_t a0[4], a1[4], br[4][4];
                LDSM4(a0, aBase + 2u * (ks * 16));
                LDSM4(a1, aBase + 2u * (16 * SA + ks * 16));
                #pragma unroll
                for (int ni = 0; ni < 4; ni++)
                    LDSM4T(br[ni], bBase + 2u * (ks * 16 * SW + ni * 16));
                #pragma unroll
                for (int ni = 0; ni < 4; ni++) {
                    MMA16816(acc[0][2 * ni], a0, br[ni][0], br[ni][1]);
                    MMA16816(acc[0][2 * ni + 1], a0, br[ni][2], br[ni][3]);
                    MMA16816(acc[1][2 * ni], a1, br[ni][0], br[ni][1]);
                    MMA16816(acc[1][2 * ni + 1], a1, br[ni][2], br[ni][3]);
                }
            }
        }

        // epilogue
        const int g = lane >> 2, q = lane & 3;
        #pragma unroll
        for (int mi = 0; mi < 2; mi++) {
            int rbase = wr + mi * 16 + g;
            int r0g = row0 + rbase;
            int r1g = r0g + 8;
            if (aout && wc < 128) {
                float p[4] = {0.f, 0.f, 0.f, 0.f};
                #pragma unroll
                for (int j = 0; j < 8; j++) {
                    float a0 = aS[wc + j * 8 + q * 2];
                    float a1 = aS[wc + j * 8 + q * 2 + 1];
                    int hh = j >> 2;
                    p[hh]     += acc[mi][j][0] * a0 + acc[mi][j][1] * a1;
                    p[2 + hh] += acc[mi][j][2] * a0 + acc[mi][j][3] * a1;
                }
                #pragma unroll
                for (int t = 0; t < 4; t++) {
                    p[t] += __shfl_xor_sync(0xffffffffu, p[t], 1);
                    p[t] += __shfl_xor_sync(0xffffffffu, p[t], 2);
                }
                if (q == 0) {
                    int headb = wc >> 5;
                    if (r0g < M) {
                        aout[(size_t)r0g * 4 + headb] = p[0];
                        aout[(size_t)r0g * 4 + headb + 1] = p[1];
                    }
                    if (r1g < M) {
                        aout[(size_t)r1g * 4 + headb] = p[2];
                        aout[(size_t)r1g * 4 + headb + 1] = p[3];
                    }
                }
            }
            #pragma unroll
            for (int j = 0; j < 8; j++) {
                int col = wc + j * 8 + q * 2;
                float* d0 = (col < 128) ? (O0 + (size_t)r0g * 128 + col)
                                        : (O1 + (size_t)r0g * 128 + col - 128);
                float* d1 = (col < 128) ? (O0 + (size_t)r1g * 128 + col)
                                        : (O1 + (size_t)r1g * 128 + col - 128);
                if (r0g < M) { float2 v = {acc[mi][j][0], acc[mi][j][1]}; *(float2*)d0 = v; }
                if (r1g < M) { float2 v = {acc[mi][j][2], acc[mi][j][3]}; *(float2*)d1 = v; }
            }
        }
    }
}

// ---------------- GAT edge kernels -------------------------------------------
__global__ void gat_logit_max(const float* __restrict__ es, const float* __restrict__ ed,
                              const int* __restrict__ src, const int* __restrict__ dst,
                              int E, float* __restrict__ elog, float* __restrict__ m) {
    int e = blockIdx.x * blockDim.x + threadIdx.x;
    if (e >= E) return;
    int s = src[e], d = dst[e];
    float4 a = *(const float4*)&es[s * 4];
    float4 b = *(const float4*)&ed[d * 4];
    float4 v; float t;
    t = a.x + b.x; v.x = t > 0.f ? t : 0.2f * t;
    t = a.y + b.y; v.y = t > 0.f ? t : 0.2f * t;
    t = a.z + b.z; v.z = t > 0.f ? t : 0.2f * t;
    t = a.w + b.w; v.w = t > 0.f ? t : 0.2f * t;
    *(float4*)&elog[e * 4] = v;
    atomicMaxFloat(&m[d * 4 + 0], v.x);
    atomicMaxFloat(&m[d * 4 + 1], v.y);
    atomicMaxFloat(&m[d * 4 + 2], v.z);
    atomicMaxFloat(&m[d * 4 + 3], v.w);
}

__global__ void gat_accum(const float* __restrict__ elog, const float* __restrict__ m,
                          float* __restrict__ ssum, const float* __restrict__ hs,
                          const int* __restrict__ src, const int* __restrict__ dst,
                          float* __restrict__ num, int E) {
    int gt = blockIdx.x * blockDim.x + threadIdx.x;
    int e = gt >> 5;
    if (e >= E) return;
    int lane = threadIdx.x & 31;
    int s = src[e], d = dst[e];
    int h = lane >> 3;
    float wv = __expf(elog[e * 4 + h] - m[d * 4 + h]);
    if ((lane & 7) == 0) atomicAdd(&ssum[d * 4 + h], wv);
    float4 hv = *(const float4*)&hs[(size_t)s * 128 + lane * 4];
    redAddV4(&num[(size_t)d * 128 + lane * 4], wv * hv.x, wv * hv.y, wv * hv.z, wv * hv.w);
}

__global__ void gat_finalize(const float* __restrict__ x, const float* __restrict__ num,
                             const float* __restrict__ ssum, const float* __restrict__ bias,
                             float* __restrict__ out, int N) {
    int gt = blockIdx.x * blockDim.x + threadIdx.x;
    int n = gt >> 5;
    int lane = threadIdx.x & 31;
    if (n >= N) return;
    int h = lane >> 3;
    float inv = 1.0f / (ssum[n * 4 + h] + 1e-16f);
    int c = lane * 4;
    float4 nv = *(const float4*)&num[(size_t)n * 128 + c];
    float4 xv = *(const float4*)&x[(size_t)n * 128 + c];
    float4 bv = *(const float4*)&bias[c];
    float4 o;
    o.x = xv.x + 0.5f * (nv.x * inv + bv.x);
    o.y = xv.y + 0.5f * (nv.y * inv + bv.y);
    o.z = xv.z + 0.5f * (nv.z * inv + bv.z);
    o.w = xv.w + 0.5f * (nv.w * inv + bv.w);
    *(float4*)&out[(size_t)n * 128 + c] = o;
}

// ---------------- GCN CSR build ----------------------------------------------
__global__ void deg_int(const int* __restrict__ dst, int E) {
    int e = blockIdx.x * blockDim.x + threadIdx.x;
    if (e < E) atomicAdd(&g_degi[dst[e]], 1);
}
__global__ void scan1() {
    __shared__ int shm[512];
    int b = blockIdx.x, t = threadIdx.x;
    int i = b * 512 + t;
    shm[t] = (i < NB) ? g_degi[i] : 0;
    __syncthreads();
    for (int s = 256; s > 0; s >>= 1) {
        if (t < s) shm[t] += shm[t + s];
        __syncthreads();
    }
    if (t == 0) g_bsum[b] = shm[0];
}
__global__ void scan2(int nblk) {
    __shared__ int shm[512];
    int t = threadIdx.x;
    shm[t] = (t < nblk) ? g_bsum[t] : 0;
    __syncthreads();
    if (t == 0) {
        int run = 0;
        for (int i = 0; i < nblk; i++) { int x = shm[i]; shm[i] = run; run += x; }
        g_off[NB] = run;
    }
    __syncthreads();
    if (t < nblk) g_bsum[t] = shm[t];
}
__global__ void scan3() {
    __shared__ int shm[512];
    int b = blockIdx.x, t = threadIdx.x;
    int i = b * 512 + t;
    int v = (i < NB) ? g_degi[i] : 0;
    shm[t] = v;
    __syncthreads();
    int x = v;
    for (int d = 1; d < 512; d <<= 1) {
        int y = (t >= d) ? shm[t - d] : 0;
        __syncthreads();
        x += y;
        shm[t] = x;
        __syncthreads();
    }
    if (i < NB) g_off[i] = g_bsum[b] + x - v;
}
__global__ void dinv_kernel() {
    int n = blockIdx.x * blockDim.x + threadIdx.x;
    if (n < NB) g_dinv[n] = rsqrtf((float)g_degi[n] + 1.0f);
}
__global__ void csr_fill(const int* __restrict__ src, const int* __restrict__ dst, int E) {
    int e = blockIdx.x * blockDim.x + threadIdx.x;
    if (e >= E) return;
    int d = dst[e];
    int slot = g_off[d] + atomicAdd(&g_cursor[d], 1);
    g_csrc[slot] = src[e];
}

// ---------------- GCN: warp per dst, register accumulate, fused epilogue -----
__global__ void __launch_bounds__(256, 8)
gcn_csr(const float* __restrict__ xb, const float* __restrict__ bg,
        float* __restrict__ out) {
    int d = blockIdx.x * 8 + (threadIdx.x >> 5);
    if (d >= NB) return;
    int lane = threadIdx.x & 31;
    int start = g_off[d], end = g_off[d + 1];
    float dv = g_dinv[d];
    float4 acc = make_float4(0.f, 0.f, 0.f, 0.f);
    for (int i = start; i < end; i++) {
        int s = g_csrc[i];
        float coef = g_dinv[s] * dv;
        float4 v = *(const float4*)&g_xwg[(size_t)s * 128 + lane * 4];
        acc.x += coef * v.x; acc.y += coef * v.y;
        acc.z += coef * v.z; acc.w += coef * v.w;
    }
    float sl = dv * dv;
    int c = lane * 4;
    float4 xw = *(const float4*)&g_xwg[(size_t)d * 128 + c];
    float4 xv = *(const float4*)&xb[(size_t)d * 128 + c];
    float4 bv = *(const float4*)&bg[c];
    float4 o;
    o.x = xv.x + 0.2f * (acc.x + xw.x * sl + bv.x);
    o.y = xv.y + 0.2f * (acc.y + xw.y * sl + bv.y);
    o.z = xv.z + 0.2f * (acc.z + xw.z * sl + bv.z);
    o.w = xv.w + 0.2f * (acc.w + xw.w * sl + bv.w);
    *(float4*)&out[(size_t)d * 128 + c] = o;
}

// ---------------- launch -----------------------------------------------------
extern "C" void kernel_launch(void* const* d_in, const int* in_sizes, int n_in,
                              void* d_out, int out_size) {
    const float* xb  = (const float*)d_in[0];
    const float* xc  = (const float*)d_in[1];
    const float* xt  = (const float*)d_in[2];
    const float* Ws1 = (const float*)d_in[3];
    const float* Wd1 = (const float*)d_in[4];
    const float* as1 = (const float*)d_in[5];
    const float* ad1 = (const float*)d_in[6];
    const float* b1  = (const float*)d_in[7];
    const float* Ws2 = (const float*)d_in[8];
    const float* Wd2 = (const float*)d_in[9];
    const float* as2 = (const float*)d_in[10];
    const float* ad2 = (const float*)d_in[11];
    const float* b2  = (const float*)d_in[12];
    const float* Wg  = (const float*)d_in[13];
    const float* bg  = (const float*)d_in[14];
    const int* b2c_s = (const int*)d_in[15];
    const int* b2c_d = (const int*)d_in[16];
    const int* c2t_s = (const int*)d_in[17];
    const int* c2t_d = (const int*)d_in[18];
    const int* adj_s = (const int*)d_in[19];
    const int* adj_d = (const int*)d_in[20];

    int Ebc  = in_sizes[15];
    int Ect  = in_sizes[17];
    int Eadj = in_sizes[19];

    float* out   = (float*)d_out;
    float* out_b = out;
    float* out_c = out + (size_t)NB * 128;
    float* out_t = out + (size_t)(NB + NC) * 128;

    // smem: 2*(2*128*136 + 2*128*(NCOLS+8)) + 512
    const int smem256 = 2 * (2 * 128 * 136 + 2 * 128 * 264) + 512;  // 205312
    const int smem128 = 2 * (2 * 128 * 136 + 2 * 128 * 136) + 512;  // 139776
    cudaFuncSetAttribute(mma_gemm<256>, cudaFuncAttributeMaxDynamicSharedMemorySize, smem256);
    cudaFuncSetAttribute(mma_gemm<128>, cudaFuncAttributeMaxDynamicSharedMemorySize, smem128);

    float *hs1, *xwg, *hd1, *hs2, *hd2, *num1, *num2;
    float *es1, *ed1, *es2, *ed2, *m1, *s1, *m2, *s2, *e1, *e2;
    cudaGetSymbolAddress((void**)&hs1, g_hs1);
    cudaGetSymbolAddress((void**)&xwg, g_xwg);
    cudaGetSymbolAddress((void**)&hd1, g_hd1);
    cudaGetSymbolAddress((void**)&hs2, g_hs2);
    cudaGetSymbolAddress((void**)&hd2, g_hd2);
    cudaGetSymbolAddress((void**)&num1, g_num1);
    cudaGetSymbolAddress((void**)&num2, g_num2);
    cudaGetSymbolAddress((void**)&es1, g_es1);
    cudaGetSymbolAddress((void**)&ed1, g_ed1);
    cudaGetSymbolAddress((void**)&es2, g_es2);
    cudaGetSymbolAddress((void**)&ed2, g_ed2);
    cudaGetSymbolAddress((void**)&m1, g_m1);
    cudaGetSymbolAddress((void**)&s1, g_s1);
    cudaGetSymbolAddress((void**)&m2, g_m2);
    cudaGetSymbolAddress((void**)&s2, g_s2);
    cudaGetSymbolAddress((void**)&e1, g_e1);
    cudaGetSymbolAddress((void**)&e2, g_e2);

    // streams/events created once on the (uncaptured) correctness call
    static cudaStream_t sB = nullptr;
    static cudaEvent_t evInit = nullptr, evDual = nullptr, evGcn = nullptr;
    if (!sB) {
        cudaStreamCreateWithFlags(&sB, cudaStreamNonBlocking);
        cudaEventCreateWithFlags(&evInit, cudaEventDisableTiming);
        cudaEventCreateWithFlags(&evDual, cudaEventDisableTiming);
        cudaEventCreateWithFlags(&evGcn, cudaEventDisableTiming);
    }

    int nblk = (NB + 511) / 512;

    // default: init
    init_kernel<<<2048, 256>>>();
    cudaEventRecord(evInit, 0);

    // side stream: CSR build (overlaps the dual GEMM)
    cudaStreamWaitEvent(sB, evInit, 0);
    deg_int<<<(Eadj + 255) / 256, 256, 0, sB>>>(adj_d, Eadj);
    scan1<<<nblk, 512, 0, sB>>>();
    scan2<<<1, 512, 0, sB>>>(nblk);
    scan3<<<nblk, 512, 0, sB>>>();
    dinv_kernel<<<(NB + 255) / 256, 256, 0, sB>>>();
    csr_fill<<<(Eadj + 255) / 256, 256, 0, sB>>>(adj_s, adj_d, Eadj);

    // default: dual GEMM (Ws1 | Wg) with fused es1
    mma_gemm<256><<<148, 512, smem256>>>(xb, NB, (NB + 127) / 128, Ws1, Wg,
                                         hs1, xwg, as1, es1);
    cudaEventRecord(evDual, 0);

    // side stream: GCN aggregation + fused epilogue (overlaps GAT chains)
    cudaStreamWaitEvent(sB, evDual, 0);
    gcn_csr<<<(NB + 7) / 8, 256, 0, sB>>>(xb, bg, out_b);
    cudaEventRecord(evGcn, sB);

    // default: cable dst transform + GAT1
    mma_gemm<128><<<148, 256, smem128>>>(xc, NC, (NC + 127) / 128, Wd1, Wd1,
                                         hd1, hd1, ad1, ed1);
    gat_logit_max<<<(Ebc + 255) / 256, 256>>>(es1, ed1, b2c_s, b2c_d, Ebc, e1, m1);
    gat_accum<<<(int)(((size_t)Ebc * 32 + 255) / 256), 256>>>(e1, m1, s1, hs1, b2c_s, b2c_d, num1, Ebc);
    gat_finalize<<<(NC * 32 + 255) / 256, 256>>>(xc, num1, s1, b1, out_c, NC);

    // default: GAT2 (updated cable -> transformer)
    mma_gemm<128><<<148, 256, smem128>>>(out_c, NC, (NC + 127) / 128, Ws2, Ws2,
                                         hs2, hs2, as2, es2);
    mma_gemm<128><<<16, 256, smem128>>>(xt, NT, (NT + 127) / 128, Wd2, Wd2,
                                        hd2, hd2, ad2, ed2);
    gat_logit_max<<<(Ect + 255) / 256, 256>>>(es2, ed2, c2t_s, c2t_d, Ect, e2, m2);
    gat_accum<<<(int)(((size_t)Ect * 32 + 255) / 256), 256>>>(e2, m2, s2, hs2, c2t_s, c2t_d, num2, Ect);
    gat_finalize<<<(NT * 32 + 255) / 256, 256>>>(xt, num2, s2, b2, out_t, NT);

    // join
    cudaStreamWaitEvent(0, evGcn, 0);
}